// round 17
// baseline (speedup 1.0000x reference)
#include <cuda_runtime.h>
#include <math.h>

#define BB 16
#define AA 3
#define CC 80
#define HH 76
#define WW 76
#define TT 50
#define PLANE (HH*WW)            // 5776
#define NPLANES (BB*AA)          // 48 conf planes
#define NT (BB*TT)               // 800 targets
#define NTHREADS 512
#define CONF_BLOCKS 82           // flat conf split
#define QPP 1444                 // float4 quads per plane
#define QTOT (NPLANES*QPP)       // 69312 quads total
#define QPB 846                  // quads per conf block (82*846=69372 >= QTOT)
#define TGT_BASE CONF_BLOCKS     // 82
#define TGT_BLOCKS 50            // 16 warps each -> 800 warps
#define DEDUPE_BASE (TGT_BASE + TGT_BLOCKS)   // 132
#define GRID 148                 // one block per SM, exactly one wave
#define BATCH_BITWORDS ((AA*PLANE + 31)/32)   // 542 words = 2.2KB
#define NSLOT 32
#define SLOT_STRIDE 64           // 256B apart -> distinct L2 slices

__constant__ float c_anch[18] = {10.f,13.f,16.f,30.f,33.f,23.f,30.f,61.f,62.f,45.f,
                                 59.f,119.f,116.f,90.f,156.f,198.f,373.f,326.f};

__device__ float g_slot[NSLOT * SLOT_STRIDE];   // zero at load; reset by tail
__device__ int   g_done = 0;                    // completion counter

// fast sigmoid: MUFU.EX2 + MUFU.RCP  (rel err ~1e-6, tolerance 1e-3)
__device__ __forceinline__ float sigf(float z) {
    return __fdividef(1.f, 1.f + __expf(-z));
}
// BCE on logits: -log(sig(v)) = softplus(-v); -log1p(-sig(v)) = softplus(v)
__device__ __forceinline__ float softplus(float x) {
    return __logf(1.f + __expf(x));
}

__device__ __forceinline__ void anchor_match(float tw, float th, int& bi) {
    float best = -1e30f; bi = 0;
    #pragma unroll
    for (int k = 0; k < 9; k++) {
        float aw = c_anch[2 * k]     * (1.f / 608.f);
        float ah = c_anch[2 * k + 1] * (1.f / 608.f);
        float inter = fminf(tw, aw) * fminf(th, ah);
        float uni   = tw * th + aw * ah - inter;
        float iou   = __fdividef(inter, uni);
        if (iou > best) { best = iou; bi = k; }
    }
}

__global__ void __launch_bounds__(NTHREADS, 1)
fused_kernel(const float* __restrict__ in,
             const float* __restrict__ tgt,
             float* __restrict__ out) {
    __shared__ unsigned bm[BATCH_BITWORDS];  // per-batch bitmap (dedupe blocks)
    __shared__ int s_islast;
    __shared__ int s_va;

    int tid = threadIdx.x;
    int l = tid & 31;
    int bid = blockIdx.x;
    float* slot = &g_slot[((bid + (tid >> 5)) & (NSLOT - 1)) * SLOT_STRIDE];

    if (bid < CONF_BLOCKS) {
        // flat conf: up to 2 quads per thread, MLP=2
        int g0 = bid * QPB + tid;
        int gend = min((bid + 1) * QPB, QTOT);
        float4 v0 = make_float4(0.f, 0.f, 0.f, 0.f);
        float4 v1 = make_float4(0.f, 0.f, 0.f, 0.f);
        bool h0 = (g0 < gend), h1 = (g0 + NTHREADS < gend);
        if (h0) {
            int p = g0 / QPP, q = g0 - p * QPP;
            int b = p / AA, a = p - b * AA;
            v0 = ((const float4*)(in + (size_t)(b * 255 + a * 85 + 4) * PLANE))[q];
        }
        if (h1) {
            int g1 = g0 + NTHREADS;
            int p = g1 / QPP, q = g1 - p * QPP;
            int b = p / AA, a = p - b * AA;
            v1 = ((const float4*)(in + (size_t)(b * 255 + a * 85 + 4) * PLANE))[q];
        }
        float s = 0.f;
        if (h0) s += sigf(v0.x) + sigf(v0.y) + sigf(v0.z) + sigf(v0.w);
        if (h1) s += sigf(v1.x) + sigf(v1.y) + sigf(v1.z) + sigf(v1.w);
        for (int o = 16; o > 0; o >>= 1) s += __shfl_down_sync(0xffffffffu, s, o);
        if (l == 0 && s != 0.f) atomicAdd(slot, s);
    } else if (bid < DEDUPE_BASE) {
        // target blocks: one warp per target; gather loads issued first
        int t = (bid - TGT_BASE) * 16 + (tid >> 5);
        const float* t5 = tgt + t * 5;
        float tc = t5[0], tx = t5[1], ty = t5[2], tw = t5[3], th = t5[4];
        int valid = ((tc + tx + ty + tw + th) != 0.f);
        int bi; anchor_match(tw, th, bi);
        bool dog = valid && (bi < AA);

        float v0 = 0.f, v1 = 0.f, v2 = 0.f;
        float tx_t = 0.f, ty_t = 0.f, tw_t = 0.f, th_t = 0.f, scale = 0.f;
        int ci = 0;
        if (dog) {
            int a_n = bi;
            int gi = (int)(tx * (float)WW); gi = min(max(gi, 0), WW - 1);
            int gj = (int)(ty * (float)HH); gj = min(max(gj, 0), HH - 1);
            int pos = gj * WW + gi;
            float aw_s = c_anch[2 * a_n], ah_s = c_anch[2 * a_n + 1];
            tx_t = tx * (float)WW - (float)gi;
            ty_t = ty * (float)HH - (float)gj;
            tw_t = __logf(tw * 608.f / aw_s);
            th_t = __logf(th * 608.f / ah_s);
            scale = 2.f * ty * tw;            // faithful to reference quirk
            ci = (int)tc;
            const float* base = in + (size_t)((t / TT) * 255 + a_n * 85) * PLANE + pos;
            v0 = base[(size_t)l * PLANE];          // loads fly during scan below
            v1 = base[(size_t)(l + 32) * PLANE];
            if (l + 64 < 85) v2 = base[(size_t)(l + 64) * PLANE];
        }

        // block-local num_truths (independent of the gather loads)
        if (tid == 0) s_va = 0;
        __syncthreads();
        {
            int va = 0;
            for (int q = tid; q < NT; q += NTHREADS) {
                const float* q5 = tgt + q * 5;
                va += ((q5[0] + q5[1] + q5[2] + q5[3] + q5[4]) != 0.f);
            }
            for (int o = 16; o > 0; o >>= 1) va += __shfl_down_sync(0xffffffffu, va, o);
            if (l == 0 && va) atomicAdd(&s_va, va);
        }
        __syncthreads();
        float inv_nt = __fdividef(1.f, fmaxf((float)s_va, 1.f));

        if (dog) {
            float acc_xy = 0.f, acc_cls = 0.f;
            if (l == 0)      acc_xy += scale * fabsf(sigf(v0) - tx_t);
            else if (l == 1) acc_xy += scale * fabsf(sigf(v0) - ty_t);
            else if (l == 2) acc_xy += scale * fabsf(v0 - tw_t);
            else if (l == 3) acc_xy += scale * fabsf(v0 - th_t);
            else if (l != 4) acc_cls += softplus((l - 5 == ci) ? -v0 : v0);
            acc_cls += softplus((l + 27 == ci) ? -v1 : v1);
            if (l + 64 < 85) acc_cls += softplus((l + 59 == ci) ? -v2 : v2);

            float acc = acc_cls + acc_xy * inv_nt;   // fold /num_truths per-warp
            for (int o = 16; o > 0; o >>= 1)
                acc += __shfl_down_sync(0xffffffffu, acc, o);
            if (l == 0) atomicAdd(slot, acc);
        }
    } else {
        // per-batch dedupe: 50 targets, 542-word bitmap
        int batch = bid - DEDUPE_BASE;
        if (tid < BATCH_BITWORDS) bm[tid] = 0u;
        if (tid + NTHREADS < BATCH_BITWORDS) bm[tid + NTHREADS] = 0u;
        __syncthreads();

        if (tid < TT) {
            const float* t5 = tgt + (batch * TT + tid) * 5;
            float tc = t5[0], tx = t5[1], ty = t5[2], tw = t5[3], th = t5[4];
            int valid = ((tc + tx + ty + tw + th) != 0.f);
            int bi; anchor_match(tw, th, bi);
            if (valid && bi < AA) {
                int gi = (int)(tx * (float)WW); gi = min(max(gi, 0), WW - 1);
                int gj = (int)(ty * (float)HH); gj = min(max(gj, 0), HH - 1);
                int cell = (bi * HH + gj) * WW + gi;   // batch-local cell
                atomicOr(&bm[cell >> 5], 1u << (cell & 31));
            }
        }
        __syncthreads();
        int un = 0;
        if (tid < BATCH_BITWORDS) un = __popc(bm[tid]);
        if (tid + NTHREADS < BATCH_BITWORDS) un += __popc(bm[tid + NTHREADS]);
        for (int o = 16; o > 0; o >>= 1) un += __shfl_down_sync(0xffffffffu, un, o);
        if (l == 0 && un) atomicAdd(slot, -(float)un);
    }

    // ── minimal completion protocol ──
    __syncthreads();                          // all warps' REDGs issued
    if (tid == 0) {
        __threadfence();                      // publish REDGs
        int old = atomicAdd(&g_done, 1);
        s_islast = (old == GRID - 1);
    }
    __syncthreads();
    if (!s_islast) return;

    // tail (last block, warp 0 only): 32 loads + shfl sum + store + reset
    if (tid < 32) {
        if (tid == 0) __threadfence();        // acquire side
        __syncwarp();
        float v = g_slot[tid * SLOT_STRIDE];
        for (int o = 16; o > 0; o >>= 1) v += __shfl_down_sync(0xffffffffu, v, o);
        if (tid == 0) out[0] = v;
        g_slot[tid * SLOT_STRIDE] = 0.f;      // reset for next graph replay
        if (tid == 0) g_done = 0;
    }
}

extern "C" void kernel_launch(void* const* d_in, const int* in_sizes, int n_in,
                              void* d_out, int out_size) {
    const float* in  = (const float*)d_in[0];   // [16, 255, 76, 76]
    const float* tgt = (const float*)d_in[1];   // [16, 250]
    float* out = (float*)d_out;
    fused_kernel<<<GRID, NTHREADS>>>(in, tgt, out);
}